// round 17
// baseline (speedup 1.0000x reference)
#include <cuda_runtime.h>

// MissHitScatter: out[4, 65536, 1024] f32.
//   out[0]    = inputs (copy, 256 MiB)
//   out[1..3] = 0      (768 MiB zero-fill; d_out poisoned to 0xAA, must write)
//
// R12: 186.0us (DRAM 91.1%). R13 (+__ldcs/__stcs): 183.4us wall / 175.2us
// kernel, DRAM 92.3%, HBM 7315 GB/s. Floor @ spec = ~168us kernel.
//
// R14 A/B (third submission; broker timeouts): uniform read:write mix. Each
// block handles one copy chunk AND the three corresponding zero chunks (same
// offset in planes 1..3), so the DRAM stream is a constant 1:4 read:write
// ratio instead of a 1:1 copy phase followed by a pure-write phase.
// Grid 8192 blocks x 256 threads.

static constexpr long long N_ELEMS = 65536LL * 1024LL;       // input f32 elements
static constexpr long long N_IN4   = N_ELEMS / 4;            // 16,777,216 float4 per plane

static constexpr int  THREADS   = 256;
static constexpr int  V_PER_THR = 8;                          // float4 per thread per plane
static constexpr long long CHUNK = (long long)THREADS * V_PER_THR;  // 2048 float4

__global__ void miss_hit_scatter_kernel(const float4* __restrict__ in4,
                                        float4* __restrict__ out4) {
    const long long base = (long long)blockIdx.x * CHUNK + threadIdx.x;
    const float4 z = make_float4(0.f, 0.f, 0.f, 0.f);

    // Front-batch the 8 streaming loads (MLP=8).
    float4 v[V_PER_THR];
#pragma unroll
    for (int i = 0; i < V_PER_THR; i++)
        v[i] = __ldcs(&in4[base + (long long)i * THREADS]);

    // Plane 0: copy.
#pragma unroll
    for (int i = 0; i < V_PER_THR; i++)
        __stcs(&out4[base + (long long)i * THREADS], v[i]);

    // Planes 1..3: zeros, same chunk offset within each plane.
#pragma unroll
    for (int p = 1; p < 4; p++) {
        const long long pbase = base + (long long)p * N_IN4;
#pragma unroll
        for (int i = 0; i < V_PER_THR; i++)
            __stcs(&out4[pbase + (long long)i * THREADS], z);
    }
}

extern "C" void kernel_launch(void* const* d_in, const int* in_sizes, int n_in,
                              void* d_out, int out_size) {
    const float4* in4 = (const float4*)d_in[0];
    float4* out4 = (float4*)d_out;

    const long long blocks = N_IN4 / CHUNK;  // 8192 (exact)
    miss_hit_scatter_kernel<<<(unsigned)blocks, THREADS>>>(in4, out4);
}